// round 1
// baseline (speedup 1.0000x reference)
#include <cuda_runtime.h>

// Problem constants (fixed by the dataset)
#define B_ROWS   16384
#define NFEAT    1024
#define FACTORS  64
#define TOTAL    524288

// ---------------------------------------------------------------------------
// Hinted 128-bit loads.
//  G table is 256 KB total and reused ~512x per row -> pin in L1 (evict_last).
//  H rows have no per-SM reuse -> evict_first so they don't thrash G out of L1.
// ---------------------------------------------------------------------------
__device__ __forceinline__ float4 ldg_evict_last4(const float4* p) {
    float4 v;
    asm("ld.global.nc.L1::evict_last.v4.f32 {%0,%1,%2,%3}, [%4];"
        : "=f"(v.x), "=f"(v.y), "=f"(v.z), "=f"(v.w) : "l"(p));
    return v;
}
__device__ __forceinline__ float4 ldg_evict_first4(const float4* p) {
    float4 v;
    asm("ld.global.nc.L1::evict_first.v4.f32 {%0,%1,%2,%3}, [%4];"
        : "=f"(v.x), "=f"(v.y), "=f"(v.z), "=f"(v.w) : "l"(p));
    return v;
}

__global__ void init_out_kernel(float* out) {
    if (threadIdx.x == 0) out[0] = 0.0f;
}

__global__ __launch_bounds__(256) void kgflex_gather_kernel(
    const int*   __restrict__ user,
    const int*   __restrict__ sample_idx,
    const int*   __restrict__ feat_idx,
    const float* __restrict__ H,
    const float* __restrict__ G,
    const float* __restrict__ K,
    float*       __restrict__ out)
{
    const int t = blockIdx.x * blockDim.x + threadIdx.x;

    float partial = 0.0f;
    if (t < TOTAL) {
        const int b = sample_idx[t];
        const int n = feat_idx[t];
        const int u = __ldg(user + b);

        // Kick off the random K gather early (longest latency, DRAM sector).
        const float kv = __ldg(K + u * NFEAT + n);

        const float4* __restrict__ Hv = (const float4*)(H + u * FACTORS);
        const float4* __restrict__ Gv = (const float4*)(G + n * FACTORS);

        // 64-dim dot, 4 independent accumulator chains (float4 lanes).
        float ax = 0.f, ay = 0.f, az = 0.f, aw = 0.f;
        #pragma unroll
        for (int i = 0; i < FACTORS / 4; ++i) {
            const float4 h = ldg_evict_first4(Hv + i);
            const float4 g = ldg_evict_last4(Gv + i);
            ax = fmaf(h.x, g.x, ax);
            ay = fmaf(h.y, g.y, ay);
            az = fmaf(h.z, g.z, az);
            aw = fmaf(h.w, g.w, aw);
        }
        partial = kv * ((ax + ay) + (az + aw));
    }

    // Warp reduction
    #pragma unroll
    for (int off = 16; off > 0; off >>= 1)
        partial += __shfl_xor_sync(0xFFFFFFFFu, partial, off);

    // Block reduction
    __shared__ float warp_sums[8];
    const int lane = threadIdx.x & 31;
    const int wid  = threadIdx.x >> 5;
    if (lane == 0) warp_sums[wid] = partial;
    __syncthreads();
    if (wid == 0) {
        float v = (lane < 8) ? warp_sums[lane] : 0.0f;
        #pragma unroll
        for (int off = 4; off > 0; off >>= 1)
            v += __shfl_xor_sync(0xFFFFFFFFu, v, off);
        if (lane == 0) atomicAdd(out, v);
    }
}

extern "C" void kernel_launch(void* const* d_in, const int* in_sizes, int n_in,
                              void* d_out, int out_size)
{
    const int*   user       = (const int*)  d_in[0];
    const int*   sample_idx = (const int*)  d_in[1];
    const int*   feat_idx   = (const int*)  d_in[2];
    const float* H          = (const float*)d_in[3];
    const float* G          = (const float*)d_in[4];
    const float* K          = (const float*)d_in[5];
    float*       out        = (float*)d_out;

    (void)in_sizes; (void)n_in; (void)out_size;

    init_out_kernel<<<1, 32>>>(out);

    const int threads = 256;
    const int blocks  = (TOTAL + threads - 1) / threads;  // 2048
    kgflex_gather_kernel<<<blocks, threads>>>(user, sample_idx, feat_idx,
                                              H, G, K, out);
}

// round 3
// speedup vs baseline: 2.8818x; 2.8818x over previous
#include <cuda_runtime.h>

#define B_ROWS   16384
#define NFEAT    1024
#define FACTORS  64
#define TOTAL    524288

// G table (256 KB) is reused ~512x per row -> pin in L1 (evict_last).
// H rows have little per-SM reuse -> evict_first.
__device__ __forceinline__ float2 ldg_el2(const float* p) {
    float2 v;
    asm("ld.global.nc.L1::evict_last.v2.f32 {%0,%1}, [%2];"
        : "=f"(v.x), "=f"(v.y) : "l"(p));
    return v;
}
__device__ __forceinline__ float2 ldg_ef2(const float* p) {
    float2 v;
    asm("ld.global.nc.L1::evict_first.v2.f32 {%0,%1}, [%2];"
        : "=f"(v.x), "=f"(v.y) : "l"(p));
    return v;
}

__global__ void init_out_kernel(float* out) {
    if (threadIdx.x == 0) out[0] = 0.0f;
}

__global__ __launch_bounds__(256) void kgflex_warpcoop_kernel(
    const int*   __restrict__ user,
    const int*   __restrict__ sample_idx,
    const int*   __restrict__ feat_idx,
    const float* __restrict__ H,
    const float* __restrict__ G,
    const float* __restrict__ K,
    float*       __restrict__ out)
{
    const int lane = threadIdx.x & 31;
    // grid 2048 x 256 = 524288 threads = 16384 warps x 32 items: exact cover.
    const int t = blockIdx.x * blockDim.x + threadIdx.x;

    // --- per-lane preload of this warp's 32 items (all coalesced/gathered once)
    const int b  = __ldg(sample_idx + t);
    const int n  = __ldg(feat_idx + t);
    const int u  = __ldg(user + b);
    const int un = (u << 10) | n;              // u*1024 + n, fits in 27 bits
    const float kv_lane = __ldg(K + un);       // K[u][n], gathered up front

    float acc = 0.0f;

    // --- warp-cooperative dot products: lanes cover factors 2*lane, 2*lane+1
    const float* Hl = H + 2 * lane;
    const float* Gl = G + 2 * lane;

    #pragma unroll
    for (int j = 0; j < 32; ++j) {
        const int   unj = __shfl_sync(0xFFFFFFFFu, un, j);
        const float kv  = __shfl_sync(0xFFFFFFFFu, kv_lane, j);
        const int hoff = (unj >> 4) & ~63;       // (un>>10)*64
        const int goff = (unj << 6) & 0xFFFF;    // (un&1023)*64

        const float2 h = ldg_ef2(Hl + hoff);     // 256B warp-coalesced
        const float2 g = ldg_el2(Gl + goff);     // 256B warp-coalesced, L1-pinned

        float p = h.x * g.x;
        p = fmaf(h.y, g.y, p);
        acc = fmaf(kv, p, acc);
    }

    // --- one reduction at the very end
    #pragma unroll
    for (int off = 16; off > 0; off >>= 1)
        acc += __shfl_xor_sync(0xFFFFFFFFu, acc, off);

    __shared__ float warp_sums[8];
    const int wid = threadIdx.x >> 5;
    if (lane == 0) warp_sums[wid] = acc;
    __syncthreads();
    if (wid == 0) {
        float v = (lane < 8) ? warp_sums[lane] : 0.0f;
        #pragma unroll
        for (int off = 4; off > 0; off >>= 1)
            v += __shfl_xor_sync(0xFFFFFFFFu, v, off);
        if (lane == 0) atomicAdd(out, v);
    }
}

extern "C" void kernel_launch(void* const* d_in, const int* in_sizes, int n_in,
                              void* d_out, int out_size)
{
    const int*   user       = (const int*)  d_in[0];
    const int*   sample_idx = (const int*)  d_in[1];
    const int*   feat_idx   = (const int*)  d_in[2];
    const float* H          = (const float*)d_in[3];
    const float* G          = (const float*)d_in[4];
    const float* K          = (const float*)d_in[5];
    float*       out        = (float*)d_out;

    (void)in_sizes; (void)n_in; (void)out_size;

    init_out_kernel<<<1, 32>>>(out);

    const int threads = 256;
    const int blocks  = TOTAL / threads;   // 2048, exact
    kgflex_warpcoop_kernel<<<blocks, threads>>>(user, sample_idx, feat_idx,
                                                H, G, K, out);
}